// round 10
// baseline (speedup 1.0000x reference)
#include <cuda_runtime.h>
#include <cuda_bf16.h>
#include <mma.h>

using namespace nvcuda;
typedef __nv_bfloat16 bf16;

#define BB    8
#define SEQ   1024
#define CDIM  1024
#define NHEAD 16
#define HD    64
#define HID   4096
#define MTOK  (BB*SEQ)           // 8192
#define NOUT1 (HID + 3*CDIM)     // 7168
#define KCAT  (HID + CDIM)       // 5120

// ------------------------- scratch (static device globals) ------------------
__device__ bf16  g_y  [(size_t)MTOK*CDIM];     // LN(x) in bf16
__device__ bf16  g_W1 [(size_t)NOUT1*CDIM];    // in_proj_w bf16
__device__ bf16  g_W2 [(size_t)CDIM*KCAT];     // folded out_proj_w bf16
__device__ float g_b2 [CDIM];                  // folded out_proj_b
__device__ bf16  g_cat[(size_t)MTOK*KCAT];     // [gelu(mlp) | x_attn]
__device__ bf16  g_Q  [(size_t)MTOK*CDIM];     // [B,H,N,D]
__device__ bf16  g_K  [(size_t)MTOK*CDIM];
__device__ bf16  g_V  [(size_t)MTOK*CDIM];

// ------------------------- weight conversion kernels ------------------------
__global__ void k_convw1(const float* __restrict__ w){
    size_t idx = ((size_t)blockIdx.x*blockDim.x + threadIdx.x)*4;
    float4 v = *(const float4*)(w + idx);
    bf16 t[4] = {__float2bfloat16(v.x), __float2bfloat16(v.y),
                 __float2bfloat16(v.z), __float2bfloat16(v.w)};
    *(uint2*)&g_W1[idx] = *(uint2*)t;
}

__global__ void k_convw2(const float* __restrict__ w){
    size_t idx = ((size_t)blockIdx.x*blockDim.x + threadIdx.x)*4;
    float4 a = *(const float4*)(w + idx);
    float4 b = *(const float4*)(w + (size_t)CDIM*KCAT + idx);
    bf16 t[4] = {__float2bfloat16(a.x+b.x), __float2bfloat16(a.y+b.y),
                 __float2bfloat16(a.z+b.z), __float2bfloat16(a.w+b.w)};
    *(uint2*)&g_W2[idx] = *(uint2*)t;
}

__global__ void k_b2(const float* __restrict__ ob){
    int c = blockIdx.x*blockDim.x + threadIdx.x;
    if (c < CDIM) g_b2[c] = ob[c] + ob[CDIM + c];
}

// ------------------------- LN over C=1024 (input) ----------------------------
__global__ void k_ln1(const float* __restrict__ x,
                      const float* __restrict__ w,
                      const float* __restrict__ b){
    int row = blockIdx.x;              // token
    int tid = threadIdx.x;             // 256 threads, 4 elems each
    const float* xr = x + (size_t)row*CDIM;
    float4 v = ((const float4*)xr)[tid];
    float s  = v.x + v.y + v.z + v.w;
    float sq = v.x*v.x + v.y*v.y + v.z*v.z + v.w*v.w;
    #pragma unroll
    for (int o = 16; o; o >>= 1){
        s  += __shfl_xor_sync(0xffffffffu, s,  o);
        sq += __shfl_xor_sync(0xffffffffu, sq, o);
    }
    __shared__ float ss[8], ssq[8];
    __shared__ float smean, srstd;
    int wp = tid >> 5, ln = tid & 31;
    if (ln == 0){ ss[wp] = s; ssq[wp] = sq; }
    __syncthreads();
    if (tid == 0){
        float S = 0.f, Q = 0.f;
        #pragma unroll
        for (int i = 0; i < 8; i++){ S += ss[i]; Q += ssq[i]; }
        float mean = S * (1.f/CDIM);
        float var  = Q * (1.f/CDIM) - mean*mean;
        smean = mean; srstd = rsqrtf(var + 1e-5f);
    }
    __syncthreads();
    float mean = smean, rs = srstd;
    float4 wv = ((const float4*)w)[tid];
    float4 bv = ((const float4*)b)[tid];
    bf16 t[4];
    t[0] = __float2bfloat16((v.x-mean)*rs*wv.x + bv.x);
    t[1] = __float2bfloat16((v.y-mean)*rs*wv.y + bv.y);
    t[2] = __float2bfloat16((v.z-mean)*rs*wv.z + bv.z);
    t[3] = __float2bfloat16((v.w-mean)*rs*wv.w + bv.w);
    *(uint2*)&g_y[(size_t)row*CDIM + tid*4] = *(uint2*)t;
}

// ------------------------- q/k per-head LN over D=64 ------------------------
__global__ void k_qkln(const float* __restrict__ qw, const float* __restrict__ qb,
                       const float* __restrict__ kw, const float* __restrict__ kb){
    int gwarp = (blockIdx.x*blockDim.x + threadIdx.x) >> 5;
    int lane  = threadIdx.x & 31;
    const int ROWS = BB*NHEAD*SEQ;                 // rows per tensor
    int tensor = (gwarp >= ROWS) ? 1 : 0;
    int row    = tensor ? gwarp - ROWS : gwarp;
    bf16* buf  = tensor ? g_K : g_Q;
    const float* w = tensor ? kw : qw;
    const float* b = tensor ? kb : qb;
    bf16* p = buf + (size_t)row*HD;
    float x0 = __bfloat162float(p[lane]);
    float x1 = __bfloat162float(p[lane+32]);
    float s  = x0 + x1;
    float sq = x0*x0 + x1*x1;
    #pragma unroll
    for (int o = 16; o; o >>= 1){
        s  += __shfl_xor_sync(0xffffffffu, s,  o);
        sq += __shfl_xor_sync(0xffffffffu, sq, o);
    }
    float mean = s * (1.f/HD);
    float var  = sq * (1.f/HD) - mean*mean;
    float rs   = rsqrtf(var + 1e-5f);
    p[lane]    = __float2bfloat16((x0-mean)*rs*w[lane]    + b[lane]);
    p[lane+32] = __float2bfloat16((x1-mean)*rs*w[lane+32] + b[lane+32]);
}

// ------------------------- generic bf16 NT GEMM (wmma) ----------------------
#define BM 128
#define BN 128
#define BK 32
#define LDS 40
#define LDC 132
#define GEMM_SMEM (BM*LDC*4)   // 67584, > 2*(BM+BN)*LDS*2 = 40960

__device__ __forceinline__ void cp16(void* s, const void* g){
    unsigned int a = (unsigned int)__cvta_generic_to_shared(s);
    asm volatile("cp.async.cg.shared.global [%0], [%1], 16;\n" :: "r"(a), "l"(g));
}

// EPI==1: A=g_y, B=g_W1, K=1024; epilogue = bias + gelu / scatter q,k,v
// EPI==2: A=g_cat, B=g_W2, K=5120; epilogue = x + ls_gamma*(acc + b2)
template<int EPI, int KD>
__global__ void __launch_bounds__(256) k_gemm(const float* __restrict__ p0,
                                              const float* __restrict__ p1,
                                              float* __restrict__ pout){
    extern __shared__ char smem[];
    bf16*  sA = (bf16*)smem;
    bf16*  sB = sA + 2*BM*LDS;
    float* sC = (float*)smem;
    const bf16* A = (EPI == 1) ? g_y  : g_cat;
    const bf16* B = (EPI == 1) ? g_W1 : g_W2;
    int bx = blockIdx.x, by = blockIdx.y;
    int tid = threadIdx.x;
    const bf16* Ab = A + (size_t)by*BM*KD;
    const bf16* Bb = B + (size_t)bx*BN*KD;

    wmma::fragment<wmma::accumulator,16,16,16,float> acc[2][4];
    #pragma unroll
    for (int i = 0; i < 2; i++)
        #pragma unroll
        for (int j = 0; j < 4; j++) wmma::fill_fragment(acc[i][j], 0.f);

    int warp = tid >> 5, wm = warp >> 1, wn = warp & 1;
    const int KT = KD / BK;

    auto load_stage = [&](int st, int kt){
        int k0 = kt*BK;
        #pragma unroll
        for (int i = 0; i < 2; i++){
            int ch = tid + i*256;
            int r = ch >> 2, c8 = (ch & 3) * 8;
            cp16(&sA[(size_t)st*BM*LDS + r*LDS + c8], Ab + (size_t)r*KD + k0 + c8);
            cp16(&sB[(size_t)st*BM*LDS + r*LDS + c8], Bb + (size_t)r*KD + k0 + c8);
        }
        asm volatile("cp.async.commit_group;\n");
    };

    load_stage(0, 0);
    for (int kt = 0; kt < KT; kt++){
        if (kt + 1 < KT){
            load_stage((kt+1) & 1, kt+1);
            asm volatile("cp.async.wait_group 1;\n");
        } else {
            asm volatile("cp.async.wait_group 0;\n");
        }
        __syncthreads();
        const bf16* pA = &sA[(size_t)(kt & 1)*BM*LDS];
        const bf16* pB = &sB[(size_t)(kt & 1)*BM*LDS];
        #pragma unroll
        for (int kk = 0; kk < BK; kk += 16){
            wmma::fragment<wmma::matrix_a,16,16,16,bf16,wmma::row_major> a[2];
            wmma::fragment<wmma::matrix_b,16,16,16,bf16,wmma::col_major> bfr[4];
            #pragma unroll
            for (int i = 0; i < 2; i++)
                wmma::load_matrix_sync(a[i], pA + (wm*32 + i*16)*LDS + kk, LDS);
            #pragma unroll
            for (int j = 0; j < 4; j++)
                wmma::load_matrix_sync(bfr[j], pB + (wn*64 + j*16)*LDS + kk, LDS);
            #pragma unroll
            for (int i = 0; i < 2; i++)
                #pragma unroll
                for (int j = 0; j < 4; j++)
                    wmma::mma_sync(acc[i][j], a[i], bfr[j], acc[i][j]);
        }
        __syncthreads();
    }

    // epilogue: stage accumulators in shared, then transform per element
    #pragma unroll
    for (int i = 0; i < 2; i++)
        #pragma unroll
        for (int j = 0; j < 4; j++)
            wmma::store_matrix_sync(&sC[(wm*32 + i*16)*LDC + wn*64 + j*16],
                                    acc[i][j], LDC, wmma::mem_row_major);
    __syncthreads();

    #pragma unroll 4
    for (int e = 0; e < 64; e++){
        int idx = tid + e*256;          // 0..16383
        int r = idx >> 7, c = idx & 127;
        float v = sC[r*LDC + c];
        int m = by*BM + r;              // token
        int o = bx*BN + c;              // output feature
        if (EPI == 1){
            // reference bias layout: bias = concat(zeros(3C), mlp_bias)
            if (o >= 3*CDIM) v += p0[o - 3*CDIM];
            if (o < HID){
                float g = 0.5f * v * (1.f + erff(v * 0.70710678118654752f));
                g_cat[(size_t)m*KCAT + o] = __float2bfloat16(g);
            } else {
                int c2 = o - HID;
                int reg = c2 >> 10;     // 0=q, 1=k, 2=v
                int cc  = c2 & 1023;
                int h = cc >> 6, d = cc & 63;
                int b = m >> 10, n = m & 1023;
                size_t off = ((size_t)(b*NHEAD + h)*SEQ + n)*HD + d;
                bf16 val = __float2bfloat16(v);
                if (reg == 0)      g_Q[off] = val;
                else if (reg == 1) g_K[off] = val;
                else               g_V[off] = val;
            }
        } else {
            size_t oi = (size_t)m*CDIM + o;
            pout[oi] = p0[oi] + p1[o] * (v + g_b2[o]);   // x + ls_gamma*(...)
        }
    }
}

// ------------------------- flash attention (64x64 tiles) --------------------
#define LQK 72
#define LSF 68
#define ATTN_SMEM (4*64*LQK*2 + 2*64*LSF*4 + 3*64*4)   // 72448

__global__ void __launch_bounds__(128) k_attn(){
    extern __shared__ char sm_[];
    bf16*  sQ = (bf16*)sm_;
    bf16*  sK = sQ + 64*LQK;
    bf16*  sV = sK + 64*LQK;
    bf16*  sP = sV + 64*LQK;
    float* sS = (float*)(sP + 64*LQK);
    float* sO = sS + 64*LSF;
    float* sM = sO + 64*LSF;
    float* sL = sM + 64;
    float* sAl = sL + 64;

    int bid = blockIdx.x;
    int qt = bid & 15, bh = bid >> 4;   // bh in [0, B*H)
    int tid = threadIdx.x;
    const bf16* Qb = g_Q + (size_t)bh*SEQ*HD;
    const bf16* Kb = g_K + (size_t)bh*SEQ*HD;
    const bf16* Vb = g_V + (size_t)bh*SEQ*HD;

    #pragma unroll
    for (int i = 0; i < 4; i++){
        int ch = tid + i*128;
        int r = ch >> 3, c8 = (ch & 7) * 8;
        *(float4*)&sQ[r*LQK + c8] = *(const float4*)&Qb[(size_t)(qt*64 + r)*HD + c8];
    }
    for (int i = tid; i < 64*LSF; i += 128) sO[i] = 0.f;
    if (tid < 64){ sM[tid] = -1e30f; sL[tid] = 0.f; }
    __syncthreads();

    int w = tid >> 5;
    for (int j = 0; j < 16; j++){
        #pragma unroll
        for (int i = 0; i < 4; i++){
            int ch = tid + i*128;
            int r = ch >> 3, c8 = (ch & 7) * 8;
            *(float4*)&sK[r*LQK + c8] = *(const float4*)&Kb[(size_t)(j*64 + r)*HD + c8];
            *(float4*)&sV[r*LQK + c8] = *(const float4*)&Vb[(size_t)(j*64 + r)*HD + c8];
        }
        __syncthreads();

        { // S = scale * Q @ K^T  (warp w owns rows w*16..w*16+15)
            wmma::fragment<wmma::accumulator,16,16,16,float> s[4];
            #pragma unroll
            for (int n = 0; n < 4; n++) wmma::fill_fragment(s[n], 0.f);
            #pragma unroll
            for (int kk = 0; kk < 64; kk += 16){
                wmma::fragment<wmma::matrix_a,16,16,16,bf16,wmma::row_major> a;
                wmma::load_matrix_sync(a, sQ + (w*16)*LQK + kk, LQK);
                #pragma unroll
                for (int n = 0; n < 4; n++){
                    wmma::fragment<wmma::matrix_b,16,16,16,bf16,wmma::col_major> bfr;
                    wmma::load_matrix_sync(bfr, sK + (n*16)*LQK + kk, LQK);
                    wmma::mma_sync(s[n], a, bfr, s[n]);
                }
            }
            #pragma unroll
            for (int n = 0; n < 4; n++){
                #pragma unroll
                for (int e = 0; e < s[n].num_elements; e++) s[n].x[e] *= 0.125f;
                wmma::store_matrix_sync(sS + (w*16)*LSF + n*16, s[n], LSF, wmma::mem_row_major);
            }
        }
        __syncthreads();

        if (tid < 64){  // online softmax row update
            float* sr = sS + tid*LSF;
            float mold = sM[tid];
            float ml = -1e30f;
            #pragma unroll 8
            for (int c = 0; c < 64; c++) ml = fmaxf(ml, sr[c]);
            float mnew  = fmaxf(mold, ml);
            float alpha = __expf(mold - mnew);
            float sum = 0.f;
            bf16* pr = sP + tid*LQK;
            #pragma unroll 8
            for (int c = 0; c < 64; c++){
                float p = __expf(sr[c] - mnew);
                sum += p;
                pr[c] = __float2bfloat16(p);
            }
            sM[tid] = mnew;
            sL[tid] = sL[tid]*alpha + sum;
            sAl[tid] = alpha;
        }
        __syncthreads();

        for (int i = tid; i < 64*64; i += 128){
            int r = i >> 6, c = i & 63;
            sO[r*LSF + c] *= sAl[r];
        }
        __syncthreads();

        { // O += P @ V
            wmma::fragment<wmma::matrix_a,16,16,16,bf16,wmma::row_major> a[4];
            #pragma unroll
            for (int kk = 0; kk < 4; kk++)
                wmma::load_matrix_sync(a[kk], sP + (w*16)*LQK + kk*16, LQK);
            #pragma unroll
            for (int n = 0; n < 4; n++){
                wmma::fragment<wmma::accumulator,16,16,16,float> cf;
                wmma::load_matrix_sync(cf, sO + (w*16)*LSF + n*16, LSF, wmma::mem_row_major);
                #pragma unroll
                for (int kk = 0; kk < 4; kk++){
                    wmma::fragment<wmma::matrix_b,16,16,16,bf16,wmma::row_major> bfr;
                    wmma::load_matrix_sync(bfr, sV + (kk*16)*LQK + n*16, LQK);
                    wmma::mma_sync(cf, a[kk], bfr, cf);
                }
                wmma::store_matrix_sync(sO + (w*16)*LSF + n*16, cf, LSF, wmma::mem_row_major);
            }
        }
        __syncthreads();
    }

    if (tid < 64){
        float inv = 1.f / sL[tid];
        int b = bh >> 4, h = bh & 15;
        int n = qt*64 + tid;
        bf16* dst = g_cat + (size_t)(b*SEQ + n)*KCAT + HID + h*64;
        #pragma unroll 8
        for (int c = 0; c < 64; c++)
            dst[c] = __float2bfloat16(sO[tid*LSF + c] * inv);
    }
}

// ------------------------- launch --------------------------------------------
extern "C" void kernel_launch(void* const* d_in, const int* in_sizes, int n_in,
                              void* d_out, int out_size){
    (void)in_sizes; (void)n_in; (void)out_size;
    const float* x     = (const float*)d_in[0];
    const float* inw   = (const float*)d_in[1];
    const float* inb   = (const float*)d_in[2];
    const float* w1    = (const float*)d_in[3];
    const float* mbias = (const float*)d_in[4];
    const float* qw    = (const float*)d_in[5];
    const float* qb    = (const float*)d_in[6];
    const float* kw    = (const float*)d_in[7];
    const float* kb    = (const float*)d_in[8];
    const float* w2    = (const float*)d_in[9];
    const float* ob    = (const float*)d_in[10];
    const float* lsg   = (const float*)d_in[11];
    float* out = (float*)d_out;

    cudaFuncSetAttribute(k_gemm<1, CDIM>, cudaFuncAttributeMaxDynamicSharedMemorySize, GEMM_SMEM);
    cudaFuncSetAttribute(k_gemm<2, KCAT>, cudaFuncAttributeMaxDynamicSharedMemorySize, GEMM_SMEM);
    cudaFuncSetAttribute(k_attn,          cudaFuncAttributeMaxDynamicSharedMemorySize, ATTN_SMEM);

    k_convw1<<<(NOUT1*CDIM/4)/256, 256>>>(w1);
    k_convw2<<<(CDIM*KCAT/4)/256, 256>>>(w2);
    k_b2<<<4, 256>>>(ob);
    k_ln1<<<MTOK, 256>>>(x, inw, inb);

    dim3 g1(NOUT1/BN, MTOK/BM);
    k_gemm<1, CDIM><<<g1, 256, GEMM_SMEM>>>(mbias, nullptr, nullptr);

    k_qkln<<<(2*BB*NHEAD*SEQ)/8, 256>>>(qw, qb, kw, kb);

    k_attn<<<BB*NHEAD*(SEQ/64), 128, ATTN_SMEM>>>();

    dim3 g2(CDIM/BN, MTOK/BM);
    k_gemm<2, KCAT><<<g2, 256, GEMM_SMEM>>>(x, lsg, out);
}

// round 14
// speedup vs baseline: 1.0075x; 1.0075x over previous
#include <cuda_runtime.h>
#include <cuda_bf16.h>
#include <mma.h>
#include <cstdint>

using namespace nvcuda;
typedef __nv_bfloat16 bf16;

#define BB    8
#define SEQ   1024
#define CDIM  1024
#define NHEAD 16
#define HD    64
#define HID   4096
#define MTOK  (BB*SEQ)           // 8192
#define NOUT1 (HID + 3*CDIM)     // 7168
#define KCAT  (HID + CDIM)       // 5120

// ------------------------- scratch (static device globals) ------------------
__device__ bf16  g_y  [(size_t)MTOK*CDIM];     // LN(x) in bf16
__device__ bf16  g_W1 [(size_t)NOUT1*CDIM];    // in_proj_w bf16
__device__ bf16  g_W2 [(size_t)CDIM*KCAT];     // folded out_proj_w bf16
__device__ float g_b2 [CDIM];                  // folded out_proj_b
__device__ bf16  g_cat[(size_t)MTOK*KCAT];     // [gelu(mlp) | x_attn]
__device__ bf16  g_Q  [(size_t)MTOK*CDIM];     // [B,H,N,D]
__device__ bf16  g_K  [(size_t)MTOK*CDIM];
__device__ bf16  g_V  [(size_t)MTOK*CDIM];

// ------------------------- weight conversion kernels ------------------------
__global__ void k_convw1(const float* __restrict__ w){
    size_t idx = ((size_t)blockIdx.x*blockDim.x + threadIdx.x)*4;
    float4 v = *(const float4*)(w + idx);
    bf16 t[4] = {__float2bfloat16(v.x), __float2bfloat16(v.y),
                 __float2bfloat16(v.z), __float2bfloat16(v.w)};
    *(uint2*)&g_W1[idx] = *(uint2*)t;
}

__global__ void k_convw2(const float* __restrict__ w){
    size_t idx = ((size_t)blockIdx.x*blockDim.x + threadIdx.x)*4;
    float4 a = *(const float4*)(w + idx);
    float4 b = *(const float4*)(w + (size_t)CDIM*KCAT + idx);
    bf16 t[4] = {__float2bfloat16(a.x+b.x), __float2bfloat16(a.y+b.y),
                 __float2bfloat16(a.z+b.z), __float2bfloat16(a.w+b.w)};
    *(uint2*)&g_W2[idx] = *(uint2*)t;
}

__global__ void k_b2(const float* __restrict__ ob){
    int c = blockIdx.x*blockDim.x + threadIdx.x;
    if (c < CDIM) g_b2[c] = ob[c] + ob[CDIM + c];
}

// ------------------------- LN over C=1024 (input) ----------------------------
__global__ void k_ln1(const float* __restrict__ x,
                      const float* __restrict__ w,
                      const float* __restrict__ b){
    int row = blockIdx.x;
    int tid = threadIdx.x;
    const float* xr = x + (size_t)row*CDIM;
    float4 v = ((const float4*)xr)[tid];
    float s  = v.x + v.y + v.z + v.w;
    float sq = v.x*v.x + v.y*v.y + v.z*v.z + v.w*v.w;
    #pragma unroll
    for (int o = 16; o; o >>= 1){
        s  += __shfl_xor_sync(0xffffffffu, s,  o);
        sq += __shfl_xor_sync(0xffffffffu, sq, o);
    }
    __shared__ float ss[8], ssq[8];
    __shared__ float smean, srstd;
    int wp = tid >> 5, ln = tid & 31;
    if (ln == 0){ ss[wp] = s; ssq[wp] = sq; }
    __syncthreads();
    if (tid == 0){
        float S = 0.f, Q = 0.f;
        #pragma unroll
        for (int i = 0; i < 8; i++){ S += ss[i]; Q += ssq[i]; }
        float mean = S * (1.f/CDIM);
        float var  = Q * (1.f/CDIM) - mean*mean;
        smean = mean; srstd = rsqrtf(var + 1e-5f);
    }
    __syncthreads();
    float mean = smean, rs = srstd;
    float4 wv = ((const float4*)w)[tid];
    float4 bv = ((const float4*)b)[tid];
    bf16 t[4];
    t[0] = __float2bfloat16((v.x-mean)*rs*wv.x + bv.x);
    t[1] = __float2bfloat16((v.y-mean)*rs*wv.y + bv.y);
    t[2] = __float2bfloat16((v.z-mean)*rs*wv.z + bv.z);
    t[3] = __float2bfloat16((v.w-mean)*rs*wv.w + bv.w);
    *(uint2*)&g_y[(size_t)row*CDIM + tid*4] = *(uint2*)t;
}

// ------------------------- q/k per-head LN over D=64 ------------------------
__global__ void k_qkln(const float* __restrict__ qw, const float* __restrict__ qb,
                       const float* __restrict__ kw, const float* __restrict__ kb){
    int gwarp = (blockIdx.x*blockDim.x + threadIdx.x) >> 5;
    int lane  = threadIdx.x & 31;
    const int ROWS = BB*NHEAD*SEQ;
    int tensor = (gwarp >= ROWS) ? 1 : 0;
    int row    = tensor ? gwarp - ROWS : gwarp;
    bf16* buf  = tensor ? g_K : g_Q;
    const float* w = tensor ? kw : qw;
    const float* b = tensor ? kb : qb;
    bf16* p = buf + (size_t)row*HD;
    float x0 = __bfloat162float(p[lane]);
    float x1 = __bfloat162float(p[lane+32]);
    float s  = x0 + x1;
    float sq = x0*x0 + x1*x1;
    #pragma unroll
    for (int o = 16; o; o >>= 1){
        s  += __shfl_xor_sync(0xffffffffu, s,  o);
        sq += __shfl_xor_sync(0xffffffffu, sq, o);
    }
    float mean = s * (1.f/HD);
    float var  = sq * (1.f/HD) - mean*mean;
    float rs   = rsqrtf(var + 1e-5f);
    p[lane]    = __float2bfloat16((x0-mean)*rs*w[lane]    + b[lane]);
    p[lane+32] = __float2bfloat16((x1-mean)*rs*w[lane+32] + b[lane+32]);
}

// ------------------------- bf16 NT GEMM (wmma, 128x256, BK=64) --------------
#define BM 128
#define BN 256
#define BK 64
#define LDS 72                      // halves stride per smem row (64 data + 8 pad)
#define LDC 260                     // floats stride for epilogue staging
#define GEMM_SMEM (BM*LDC*4)        // 133120 > 2*(BM+BN)*LDS*2 = 110592

__device__ __forceinline__ void cp16(void* s, const void* g){
    unsigned int a = (unsigned int)__cvta_generic_to_shared(s);
    asm volatile("cp.async.cg.shared.global [%0], [%1], 16;\n" :: "r"(a), "l"(g));
}

// EPI==1: A=g_y, B=g_W1, K=1024; epilogue = bias + gelu / scatter q,k,v (p0=mlp_bias)
// EPI==2: A=g_cat, B=g_W2, K=5120; epilogue = x + ls_gamma*(acc + b2) (p0=x, p1=lsg)
template<int EPI, int KD>
__global__ void __launch_bounds__(256) k_gemm(const float* __restrict__ p0,
                                              const float* __restrict__ p1,
                                              float* __restrict__ pout){
    extern __shared__ char smem[];
    bf16*  sA = (bf16*)smem;                    // 2 stages x BM x LDS
    bf16*  sB = sA + 2*BM*LDS;                  // 2 stages x BN x LDS
    float* sC = (float*)smem;                   // epilogue overlay
    const bf16* A = (EPI == 1) ? g_y  : g_cat;
    const bf16* B = (EPI == 1) ? g_W1 : g_W2;
    int bx = blockIdx.x, by = blockIdx.y;
    int tid = threadIdx.x;
    const bf16* Ab = A + (size_t)by*BM*KD;
    const bf16* Bb = B + (size_t)bx*BN*KD;

    wmma::fragment<wmma::accumulator,16,16,16,float> acc[4][4];
    #pragma unroll
    for (int i = 0; i < 4; i++)
        #pragma unroll
        for (int j = 0; j < 4; j++) wmma::fill_fragment(acc[i][j], 0.f);

    int warp = tid >> 5, wm = warp >> 2, wn = warp & 3;   // 2 x 4 warps, 64x64 tiles
    const int KT = KD / BK;

    auto load_stage = [&](int st, int kt){
        int k0 = kt*BK;
        // A: 128 rows x 8 segs of 16B (=8 halves); 1024 chunks / 256 thr = 4
        #pragma unroll
        for (int i = 0; i < 4; i++){
            int ch = tid + i*256;
            int r = ch >> 3, s8 = (ch & 7) * 8;
            cp16(&sA[(size_t)st*BM*LDS + r*LDS + s8], Ab + (size_t)r*KD + k0 + s8);
        }
        // B: 256 rows x 8 segs; 2048 chunks / 256 thr = 8
        #pragma unroll
        for (int i = 0; i < 8; i++){
            int ch = tid + i*256;
            int r = ch >> 3, s8 = (ch & 7) * 8;
            cp16(&sB[(size_t)st*BN*LDS + r*LDS + s8], Bb + (size_t)r*KD + k0 + s8);
        }
        asm volatile("cp.async.commit_group;\n");
    };

    load_stage(0, 0);
    for (int kt = 0; kt < KT; kt++){
        if (kt + 1 < KT){
            load_stage((kt+1) & 1, kt+1);
            asm volatile("cp.async.wait_group 1;\n");
        } else {
            asm volatile("cp.async.wait_group 0;\n");
        }
        __syncthreads();
        const bf16* pA = &sA[(size_t)(kt & 1)*BM*LDS];
        const bf16* pB = &sB[(size_t)(kt & 1)*BN*LDS];
        #pragma unroll
        for (int kk = 0; kk < BK; kk += 16){
            wmma::fragment<wmma::matrix_a,16,16,16,bf16,wmma::row_major> a[4];
            #pragma unroll
            for (int i = 0; i < 4; i++)
                wmma::load_matrix_sync(a[i], pA + (wm*64 + i*16)*LDS + kk, LDS);
            #pragma unroll
            for (int j = 0; j < 4; j++){
                wmma::fragment<wmma::matrix_b,16,16,16,bf16,wmma::col_major> bfr;
                wmma::load_matrix_sync(bfr, pB + (wn*64 + j*16)*LDS + kk, LDS);
                #pragma unroll
                for (int i = 0; i < 4; i++)
                    wmma::mma_sync(acc[i][j], a[i], bfr, acc[i][j]);
            }
        }
        __syncthreads();
    }

    // epilogue: stage accumulators in shared, then transform per element
    #pragma unroll
    for (int i = 0; i < 4; i++)
        #pragma unroll
        for (int j = 0; j < 4; j++)
            wmma::store_matrix_sync(&sC[(wm*64 + i*16)*LDC + wn*64 + j*16],
                                    acc[i][j], LDC, wmma::mem_row_major);
    __syncthreads();

    // 128 rows x 256 cols; thread tid handles column tid of row e (coalesced)
    #pragma unroll 2
    for (int e = 0; e < BM; e++){
        int r = e, c = tid;
        float v = sC[r*LDC + c];
        int m = by*BM + r;              // token
        int o = bx*BN + c;              // output feature
        if (EPI == 1){
            // reference bias layout: bias = concat(zeros(3C), mlp_bias)
            if (o >= 3*CDIM) v += p0[o - 3*CDIM];
            if (o < HID){
                float g = 0.5f * v * (1.f + erff(v * 0.70710678118654752f));
                g_cat[(size_t)m*KCAT + o] = __float2bfloat16(g);
            } else {
                int c2 = o - HID;
                int reg = c2 >> 10;     // 0=q, 1=k, 2=v
                int cc  = c2 & 1023;
                int h = cc >> 6, d = cc & 63;
                int b = m >> 10, n = m & 1023;
                size_t off = ((size_t)(b*NHEAD + h)*SEQ + n)*HD + d;
                bf16 val = __float2bfloat16(v);
                if (reg == 0)      g_Q[off] = val;
                else if (reg == 1) g_K[off] = val;
                else               g_V[off] = val;
            }
        } else {
            size_t oi = (size_t)m*CDIM + o;
            pout[oi] = p0[oi] + p1[o] * (v + g_b2[o]);   // x + ls_gamma*(...)
        }
    }
}

// ------------------------- flash attention (64x64 tiles) --------------------
#define LQK 72
#define LSF 68
#define ATTN_SMEM (4*64*LQK*2 + 2*64*LSF*4 + 3*64*4)   // 72448

__global__ void __launch_bounds__(128) k_attn(){
    extern __shared__ char sm_[];
    bf16*  sQ = (bf16*)sm_;
    bf16*  sK = sQ + 64*LQK;
    bf16*  sV = sK + 64*LQK;
    bf16*  sP = sV + 64*LQK;
    float* sS = (float*)(sP + 64*LQK);
    float* sO = sS + 64*LSF;
    float* sM = sO + 64*LSF;
    float* sL = sM + 64;
    float* sAl = sL + 64;

    int bid = blockIdx.x;
    int qt = bid & 15, bh = bid >> 4;
    int tid = threadIdx.x;
    const bf16* Qb = g_Q + (size_t)bh*SEQ*HD;
    const bf16* Kb = g_K + (size_t)bh*SEQ*HD;
    const bf16* Vb = g_V + (size_t)bh*SEQ*HD;

    #pragma unroll
    for (int i = 0; i < 4; i++){
        int ch = tid + i*128;
        int r = ch >> 3, c8 = (ch & 7) * 8;
        *(float4*)&sQ[r*LQK + c8] = *(const float4*)&Qb[(size_t)(qt*64 + r)*HD + c8];
    }
    for (int i = tid; i < 64*LSF; i += 128) sO[i] = 0.f;
    if (tid < 64){ sM[tid] = -1e30f; sL[tid] = 0.f; }
    __syncthreads();

    int w = tid >> 5;
    for (int j = 0; j < 16; j++){
        #pragma unroll
        for (int i = 0; i < 4; i++){
            int ch = tid + i*128;
            int r = ch >> 3, c8 = (ch & 7) * 8;
            *(float4*)&sK[r*LQK + c8] = *(const float4*)&Kb[(size_t)(j*64 + r)*HD + c8];
            *(float4*)&sV[r*LQK + c8] = *(const float4*)&Vb[(size_t)(j*64 + r)*HD + c8];
        }
        __syncthreads();

        { // S = scale * Q @ K^T
            wmma::fragment<wmma::accumulator,16,16,16,float> s[4];
            #pragma unroll
            for (int n = 0; n < 4; n++) wmma::fill_fragment(s[n], 0.f);
            #pragma unroll
            for (int kk = 0; kk < 64; kk += 16){
                wmma::fragment<wmma::matrix_a,16,16,16,bf16,wmma::row_major> a;
                wmma::load_matrix_sync(a, sQ + (w*16)*LQK + kk, LQK);
                #pragma unroll
                for (int n = 0; n < 4; n++){
                    wmma::fragment<wmma::matrix_b,16,16,16,bf16,wmma::col_major> bfr;
                    wmma::load_matrix_sync(bfr, sK + (n*16)*LQK + kk, LQK);
                    wmma::mma_sync(s[n], a, bfr, s[n]);
                }
            }
            #pragma unroll
            for (int n = 0; n < 4; n++){
                #pragma unroll
                for (int e = 0; e < s[n].num_elements; e++) s[n].x[e] *= 0.125f;
                wmma::store_matrix_sync(sS + (w*16)*LSF + n*16, s[n], LSF, wmma::mem_row_major);
            }
        }
        __syncthreads();

        if (tid < 64){  // online softmax row update
            float* sr = sS + tid*LSF;
            float mold = sM[tid];
            float ml = -1e30f;
            #pragma unroll 8
            for (int c = 0; c < 64; c++) ml = fmaxf(ml, sr[c]);
            float mnew  = fmaxf(mold, ml);
            float alpha = __expf(mold - mnew);
            float sum = 0.f;
            bf16* pr = sP + tid*LQK;
            #pragma unroll 8
            for (int c = 0; c < 64; c++){
                float p = __expf(sr[c] - mnew);
                sum += p;
                pr[c] = __float2bfloat16(p);
            }
            sM[tid] = mnew;
            sL[tid] = sL[tid]*alpha + sum;
            sAl[tid] = alpha;
        }
        __syncthreads();

        for (int i = tid; i < 64*64; i += 128){
            int r = i >> 6, c = i & 63;
            sO[r*LSF + c] *= sAl[r];
        }
        __syncthreads();

        { // O += P @ V
            wmma::fragment<wmma::matrix_a,16,16,16,bf16,wmma::row_major> a[4];
            #pragma unroll
            for (int kk = 0; kk < 4; kk++)
                wmma::load_matrix_sync(a[kk], sP + (w*16)*LQK + kk*16, LQK);
            #pragma unroll
            for (int n = 0; n < 4; n++){
                wmma::fragment<wmma::accumulator,16,16,16,float> cf;
                wmma::load_matrix_sync(cf, sO + (w*16)*LSF + n*16, LSF, wmma::mem_row_major);
                #pragma unroll
                for (int kk = 0; kk < 4; kk++){
                    wmma::fragment<wmma::matrix_b,16,16,16,bf16,wmma::row_major> bfr;
                    wmma::load_matrix_sync(bfr, sV + (kk*16)*LQK + n*16, LQK);
                    wmma::mma_sync(cf, a[kk], bfr, cf);
                }
                wmma::store_matrix_sync(sO + (w*16)*LSF + n*16, cf, LSF, wmma::mem_row_major);
            }
        }
        __syncthreads();
    }

    if (tid < 64){
        float inv = 1.f / sL[tid];
        int b = bh >> 4, h = bh & 15;
        int n = qt*64 + tid;
        bf16* dst = g_cat + (size_t)(b*SEQ + n)*KCAT + HID + h*64;
        #pragma unroll 8
        for (int c = 0; c < 64; c++)
            dst[c] = __float2bfloat16(sO[tid*LSF + c] * inv);
    }
}

// ------------------------- launch --------------------------------------------
extern "C" void kernel_launch(void* const* d_in, const int* in_sizes, int n_in,
                              void* d_out, int out_size){
    (void)in_sizes; (void)n_in; (void)out_size;
    const float* x     = (const float*)d_in[0];
    const float* inw   = (const float*)d_in[1];
    const float* inb   = (const float*)d_in[2];
    const float* w1    = (const float*)d_in[3];
    const float* mbias = (const float*)d_in[4];
    const float* qw    = (const float*)d_in[5];
    const float* qb    = (const float*)d_in[6];
    const float* kw    = (const float*)d_in[7];
    const float* kb    = (const float*)d_in[8];
    const float* w2    = (const float*)d_in[9];
    const float* ob    = (const float*)d_in[10];
    const float* lsg   = (const float*)d_in[11];
    float* out = (float*)d_out;

    cudaFuncSetAttribute(k_gemm<1, CDIM>, cudaFuncAttributeMaxDynamicSharedMemorySize, GEMM_SMEM);
    cudaFuncSetAttribute(k_gemm<2, KCAT>, cudaFuncAttributeMaxDynamicSharedMemorySize, GEMM_SMEM);
    cudaFuncSetAttribute(k_attn,          cudaFuncAttributeMaxDynamicSharedMemorySize, ATTN_SMEM);

    k_convw1<<<(NOUT1*CDIM/4)/256, 256>>>(w1);
    k_convw2<<<(CDIM*KCAT/4)/256, 256>>>(w2);
    k_b2<<<4, 256>>>(ob);
    k_ln1<<<MTOK, 256>>>(x, inw, inb);

    dim3 g1(NOUT1/BN, MTOK/BM);            // (28, 64)
    k_gemm<1, CDIM><<<g1, 256, GEMM_SMEM>>>(mbias, nullptr, nullptr);

    k_qkln<<<(2*BB*NHEAD*SEQ)/8, 256>>>(qw, qb, kw, kb);

    k_attn<<<BB*NHEAD*(SEQ/64), 128, ATTN_SMEM>>>();

    dim3 g2(CDIM/BN, MTOK/BM);             // (4, 64)
    k_gemm<2, KCAT><<<g2, 256, GEMM_SMEM>>>(x, lsg, out);
}